// round 9
// baseline (speedup 1.0000x reference)
#include <cuda_runtime.h>
#include <cuda_bf16.h>
#include <cstdint>

#define ALPHA   0.2f          // DT/TAU = 20/100
#define NN      2048
#define BB      64
#define TT      200
#define NI      32
#define NO      8
#define G_CTAS  64
#define N_TILE  32            // neurons per CTA

// act staging: slot = one k-quarter (512 k = 1024 B) for all 64 batch rows.
// Row stride 1040 B (65*16B) -> conflict-free ldmatrix.
#define ROWB        1040
#define QBYTES      1024
#define Q_TX        (64 * QBYTES)      // 65536 bytes per quarter fill

// SMEM offsets
#define OFF_SLOT0   0
#define OFF_SLOT1   66560
#define OFF_REC     133120             // float[4][64][36] = 36864 B
#define REC_LD      36
#define REC_PLANE   (64 * REC_LD)
#define OFF_HSM     169984             // float[64][32] = 8192 B
#define OFF_MBAR    178176             // 4 full + 4 empty mbarriers (64 B)
#define SMEM_BYTES  178240

// ---------------- device scratch ----------------
__device__ float          d_dn[(size_t)TT * BB * NN];
__device__ float          d_act_f32[(size_t)(TT + 1) * BB * NN];
__device__ __nv_bfloat16  d_act_bf16[(size_t)(TT + 1) * BB * NN];
__device__ unsigned int   d_flags[(TT + 1) * 8];

// ---------------- PTX helpers ----------------
__device__ __forceinline__ unsigned ld_acquire_gpu(const unsigned* p) {
    unsigned v;
    asm volatile("ld.acquire.gpu.u32 %0, [%1];" : "=r"(v) : "l"(p) : "memory");
    return v;
}
__device__ __forceinline__ void mbar_init(uint32_t mbar, uint32_t count) {
    asm volatile("mbarrier.init.shared.b64 [%0], %1;" :: "r"(mbar), "r"(count) : "memory");
}
__device__ __forceinline__ void mbar_expect_tx(uint32_t mbar, uint32_t bytes) {
    asm volatile("mbarrier.arrive.expect_tx.shared.b64 _, [%0], %1;" :: "r"(mbar), "r"(bytes) : "memory");
}
__device__ __forceinline__ void mbar_arrive(uint32_t mbar) {
    asm volatile("mbarrier.arrive.shared.b64 _, [%0];" :: "r"(mbar) : "memory");
}
__device__ __forceinline__ void mbar_wait(uint32_t mbar, int parity) {
    asm volatile(
        "{\n\t.reg .pred P;\n"
        "W%=:\n\t"
        "mbarrier.try_wait.parity.shared.b64 P, [%0], %1;\n\t"
        "@P bra D%=;\n\t"
        "bra W%=;\n"
        "D%=:\n\t}"
        :: "r"(mbar), "r"(parity) : "memory");
}
__device__ __forceinline__ void bulk_cp(uint32_t dst, const void* src, uint32_t mbar) {
    asm volatile(
        "cp.async.bulk.shared::cluster.global.mbarrier::complete_tx::bytes [%0], [%1], %2, [%3];"
        :: "r"(dst), "l"(src), "r"((uint32_t)QBYTES), "r"(mbar) : "memory");
}
__device__ __forceinline__ void ldm_x4(uint32_t& a0, uint32_t& a1, uint32_t& a2, uint32_t& a3,
                                       uint32_t addr) {
    asm volatile("ldmatrix.sync.aligned.m8n8.x4.shared.b16 {%0,%1,%2,%3}, [%4];"
                 : "=r"(a0), "=r"(a1), "=r"(a2), "=r"(a3) : "r"(addr));
}
__device__ __forceinline__ void mma_16816(float& d0, float& d1, float& d2, float& d3,
                                          uint32_t a0, uint32_t a1, uint32_t a2, uint32_t a3,
                                          uint32_t b0, uint32_t b1) {
    asm volatile("mma.sync.aligned.m16n8k16.row.col.f32.bf16.bf16.f32 "
                 "{%0,%1,%2,%3}, {%4,%5,%6,%7}, {%8,%9}, {%0,%1,%2,%3};"
                 : "+f"(d0), "+f"(d1), "+f"(d2), "+f"(d3)
                 : "r"(a0), "r"(a1), "r"(a2), "r"(a3), "r"(b0), "r"(b1));
}
__device__ __forceinline__ uint32_t pack_bf16x2(float x, float y) {
    __nv_bfloat162 p = __floats2bfloat162_rn(x, y);
    return *(uint32_t*)&p;
}

// ---------------- prep: dn = alpha*(u@In_w^T + noise); act slot 0; flag init ----------------
__global__ void prep_kernel(const float* __restrict__ u,
                            const float* __restrict__ In_w,
                            const float* __restrict__ noise,
                            const float* __restrict__ h0) {
    int tid = threadIdx.x;   // 256
    if (blockIdx.y < 16) {
        int t  = blockIdx.x;
        int n0 = blockIdx.y * 128;
        __shared__ float us[BB][NI];
        __shared__ float ws[128][NI];
        for (int idx = tid; idx < BB * NI; idx += 256) {
            int b = idx / NI, i = idx % NI;
            us[b][i] = u[((size_t)b * TT + t) * NI + i];
        }
        for (int idx = tid; idx < 128 * NI; idx += 256) {
            int r = idx / NI, i = idx % NI;
            ws[r][i] = In_w[(size_t)(n0 + r) * NI + i];
        }
        __syncthreads();
        int b  = tid >> 2;
        int ns = (tid & 3) * 32;
        const float* nz  = noise + ((size_t)b * TT + t) * NN + n0 + ns;
        float*       out = d_dn  + ((size_t)t * BB + b) * NN + n0 + ns;
        for (int nn = 0; nn < 32; nn++) {
            float s = 0.f;
            #pragma unroll
            for (int i = 0; i < NI; i++) s += us[b][i] * ws[ns + nn][i];
            out[nn] = ALPHA * (s + nz[nn]);
        }
    } else {
        int base = blockIdx.x * 656;
        int end  = base + 656; if (end > BB * NN) end = BB * NN;
        for (int i = base + tid; i < end; i += 256) {
            int n = i % NN;
            float th = tanhf(h0[n]);
            d_act_f32[i]  = th;
            d_act_bf16[i] = __float2bfloat16(th);
        }
        if (blockIdx.x == 0) {
            for (int i = tid; i < (TT + 1) * 8; i += 256)
                d_flags[i] = (i < 8) ? 8u : 0u;   // slot 0 pre-complete
        }
    }
}

// ---------------- persistent recurrent kernel ----------------
extern __shared__ char smem_raw[];

__global__ void __launch_bounds__(512, 1)
rnn_kernel(const float* __restrict__ J, const float* __restrict__ h0,
           const float* __restrict__ Out_w, float* __restrict__ y) {
    float* rec = (float*)(smem_raw + OFF_REC);
    float* hsm = (float*)(smem_raw + OFF_HSM);

    const uint32_t smem_u32 = (uint32_t)__cvta_generic_to_shared(smem_raw);
    const uint32_t slot_u32[2] = { smem_u32 + OFF_SLOT0, smem_u32 + OFF_SLOT1 };
    // barrier layout: full[q] at +q*8, empty[q] at +32+q*8
    const uint32_t mb0 = smem_u32 + OFF_MBAR;

    const int tid  = threadIdx.x;
    const int cta  = blockIdx.x;
    const int u0   = cta * N_TILE;
    const int wid  = tid >> 5;
    const int lane = tid & 31;
    const int q    = wid >> 2;   // k-quarter 0..3
    const int nw   = wid & 3;    // n8 block 0..3

    if (tid == 0) {
        #pragma unroll
        for (int i = 0; i < 4; i++) {
            mbar_init(mb0 + i * 8, 1);        // full[i]: producer expect_tx
            mbar_init(mb0 + 32 + i * 8, 4);   // empty[i]: 4 consumer warps
        }
    }
    for (int idx = tid; idx < BB * N_TILE; idx += 512)
        hsm[idx] = h0[u0 + (idx & (N_TILE - 1))];
    __syncthreads();

    // ---- J -> register-resident B fragments (held for all 200 steps) ----
    const int n_row = u0 + nw * 8 + (lane >> 2);
    const int t4    = lane & 3;
    uint32_t breg[64];
    {
        const float* Jr = J + (size_t)n_row * NN + q * 512 + 2 * t4;
        #pragma unroll
        for (int ks = 0; ks < 32; ks++) {
            float2 v0 = *(const float2*)(Jr + ks * 16);
            float2 v1 = *(const float2*)(Jr + ks * 16 + 8);
            breg[2 * ks]     = pack_bf16x2(v0.x, v0.y);
            breg[2 * ks + 1] = pack_bf16x2(v1.x, v1.y);
        }
    }

    // per-lane ldmatrix constants
    const int row_in_m   = (lane & 7) + ((lane >> 3) & 1) * 8;
    const int kb         = (lane >> 4) * 16;
    const uint32_t abase = slot_u32[q & 1] + row_in_m * ROWB + kb;
    const uint32_t my_full  = mb0 + q * 8;
    const uint32_t my_empty = mb0 + 32 + q * 8;

    const float krec = ALPHA / (float)NN;
    const int   g    = lane >> 2;
    float* rp        = rec + q * REC_PLANE + nw * 8 + 2 * t4;

    for (int t = 0; t < TT; t++) {
        const int p  = t & 1;        // this step's completion parity
        const int pp = (t - 1) & 1;  // previous step's parity

        // ---------- producer (warp 15): gate on flags, 4 quarter fills ----------
        if (wid == 15) {
            if (lane < 8)
                while (ld_acquire_gpu(&d_flags[t * 8 + lane]) < 8u) { }
            __syncwarp();
            asm volatile("fence.proxy.async;" ::: "memory");
            const char* actg = (const char*)d_act_bf16 + (size_t)t * BB * NN * 2;

            // q0 -> slot0 (needs q2's consume of step t-1)
            if (t > 0) { if (lane == 0) mbar_wait(mb0 + 32 + 2 * 8, pp); __syncwarp(); }
            if (lane == 0) mbar_expect_tx(mb0 + 0 * 8, Q_TX);
            __syncwarp();
            for (int r = lane; r < 64; r += 32)
                bulk_cp(slot_u32[0] + r * ROWB, actg + (size_t)r * 4096, mb0 + 0 * 8);

            // q1 -> slot1 (needs q3's consume of step t-1)
            if (t > 0) { if (lane == 0) mbar_wait(mb0 + 32 + 3 * 8, pp); __syncwarp(); }
            if (lane == 0) mbar_expect_tx(mb0 + 1 * 8, Q_TX);
            __syncwarp();
            for (int r = lane; r < 64; r += 32)
                bulk_cp(slot_u32[1] + r * ROWB, actg + (size_t)r * 4096 + QBYTES, mb0 + 1 * 8);

            // q2 -> slot0 (needs q0's consume of step t)
            if (lane == 0) mbar_wait(mb0 + 32 + 0 * 8, p);
            __syncwarp();
            if (lane == 0) mbar_expect_tx(mb0 + 2 * 8, Q_TX);
            __syncwarp();
            for (int r = lane; r < 64; r += 32)
                bulk_cp(slot_u32[0] + r * ROWB, actg + (size_t)r * 4096 + 2 * QBYTES, mb0 + 2 * 8);

            // q3 -> slot1 (needs q1's consume of step t)
            if (lane == 0) mbar_wait(mb0 + 32 + 1 * 8, p);
            __syncwarp();
            if (lane == 0) mbar_expect_tx(mb0 + 3 * 8, Q_TX);
            __syncwarp();
            for (int r = lane; r < 64; r += 32)
                bulk_cp(slot_u32[1] + r * ROWB, actg + (size_t)r * 4096 + 3 * QBYTES, mb0 + 3 * 8);
        }

        // ---------- consume my quarter ----------
        mbar_wait(my_full, p);

        float acc[4][4];
        #pragma unroll
        for (int m = 0; m < 4; m++) {
            acc[m][0] = 0.f; acc[m][1] = 0.f; acc[m][2] = 0.f; acc[m][3] = 0.f;
        }
        #pragma unroll
        for (int ks = 0; ks < 32; ks++) {
            #pragma unroll
            for (int m = 0; m < 4; m++) {
                uint32_t a0, a1, a2, a3;
                ldm_x4(a0, a1, a2, a3, abase + m * 16 * ROWB + ks * 32);
                mma_16816(acc[m][0], acc[m][1], acc[m][2], acc[m][3],
                          a0, a1, a2, a3, breg[2 * ks], breg[2 * ks + 1]);
            }
        }
        __syncwarp();
        if (lane == 0) mbar_arrive(my_empty);

        // ---------- store rec partials ----------
        #pragma unroll
        for (int m = 0; m < 4; m++) {
            *(float2*)(rp + (m * 16 + g) * REC_LD)     = make_float2(acc[m][0], acc[m][1]);
            *(float2*)(rp + (m * 16 + g + 8) * REC_LD) = make_float2(acc[m][2], acc[m][3]);
        }
        __syncthreads();

        // ---------- fused h update + tanh + act stores ----------
        {
            int b = tid >> 3, us = (tid & 7) * 4;
            float4 r = make_float4(0.f, 0.f, 0.f, 0.f);
            #pragma unroll
            for (int qd = 0; qd < 4; qd++) {
                float4 v = *(float4*)(rec + qd * REC_PLANE + b * REC_LD + us);
                r.x += v.x; r.y += v.y; r.z += v.z; r.w += v.w;
            }
            float4 h  = *(float4*)(hsm + b * N_TILE + us);
            float4 dn = *(const float4*)(d_dn + ((size_t)t * BB + b) * NN + u0 + us);
            float4 hn;
            hn.x = (1.f - ALPHA) * h.x + krec * r.x + dn.x;
            hn.y = (1.f - ALPHA) * h.y + krec * r.y + dn.y;
            hn.z = (1.f - ALPHA) * h.z + krec * r.z + dn.z;
            hn.w = (1.f - ALPHA) * h.w + krec * r.w + dn.w;
            *(float4*)(hsm + b * N_TILE + us) = hn;
            float4 th;
            th.x = tanhf(hn.x); th.y = tanhf(hn.y); th.z = tanhf(hn.z); th.w = tanhf(hn.w);
            size_t off = ((size_t)(t + 1) * BB + b) * NN + u0 + us;
            *(float4*)(d_act_f32 + off) = th;
            __nv_bfloat162 lo = __floats2bfloat162_rn(th.x, th.y);
            __nv_bfloat162 hi = __floats2bfloat162_rn(th.z, th.w);
            *(uint2*)(d_act_bf16 + off) = make_uint2(*(unsigned*)&lo, *(unsigned*)&hi);
        }
        __syncthreads();
        if (tid == 0) {
            __threadfence();
            atomicAdd(&d_flags[(t + 1) * 8 + (cta >> 3)], 1u);
        }
    }

    // ---- output projection tail: y[b,t,o] = (1/N) sum_n Out[n,o]*tanh(h_t[b,n]) ----
    float* ps = rec;  // reuse as [64][8][8]
    for (int t = cta; t <= TT; t += G_CTAS) {
        if (tid < 8)
            while (ld_acquire_gpu(&d_flags[t * 8 + tid]) < 8u) { }
        __syncthreads();
        int b = tid >> 3, s = tid & 7;
        float a0 = 0, a1 = 0, a2 = 0, a3 = 0, a4 = 0, a5 = 0, a6 = 0, a7 = 0;
        const float* ap = d_act_f32 + ((size_t)t * BB + b) * NN + s * 256;
        for (int n = 0; n < 256; n++) {
            float a = ap[n];
            const float4* w = (const float4*)(Out_w + (size_t)(s * 256 + n) * NO);
            float4 w0 = w[0], w1 = w[1];
            a0 += a * w0.x; a1 += a * w0.y; a2 += a * w0.z; a3 += a * w0.w;
            a4 += a * w1.x; a5 += a * w1.y; a6 += a * w1.z; a7 += a * w1.w;
        }
        float* pp = ps + (b * 8 + s) * 8;
        pp[0] = a0; pp[1] = a1; pp[2] = a2; pp[3] = a3;
        pp[4] = a4; pp[5] = a5; pp[6] = a6; pp[7] = a7;
        __syncthreads();
        if (tid < BB * NO) {
            int bb = tid / NO, o = tid % NO;
            float ssum = 0.f;
            #pragma unroll
            for (int k = 0; k < 8; k++) ssum += ps[(bb * 8 + k) * 8 + o];
            y[((size_t)bb * (TT + 1) + t) * NO + o] = ssum / (float)NN;
        }
        __syncthreads();
    }
}

// ---------------- launcher ----------------
extern "C" void kernel_launch(void* const* d_in, const int* in_sizes, int n_in,
                              void* d_out, int out_size) {
    const float* u     = (const float*)d_in[0];
    const float* In_w  = (const float*)d_in[1];
    const float* Out_w = (const float*)d_in[2];
    const float* J     = (const float*)d_in[3];
    const float* h0    = (const float*)d_in[4];
    const float* noise = (const float*)d_in[5];
    float*       y     = (float*)d_out;

    cudaFuncSetAttribute(rnn_kernel, cudaFuncAttributeMaxDynamicSharedMemorySize, SMEM_BYTES);

    dim3 gprep(TT, 17);
    prep_kernel<<<gprep, 256>>>(u, In_w, noise, h0);
    rnn_kernel<<<G_CTAS, 512, SMEM_BYTES>>>(J, h0, Out_w, y);
}